// round 3
// baseline (speedup 1.0000x reference)
#include <cuda_runtime.h>
#include <math.h>

#define BATCH   256
#define LATENT  64
#define HID     256
#define GATES   1024   // 4*HID
#define OUTD    128
#define SEQ     512

#define CLUSTER   8        // CTAs per cluster (hidden split)
#define NCLUSTER  16       // clusters (batch split)
#define ROWS      16       // batch rows per cluster
#define NLOC      128      // gate cols per CTA (4 gates x 32 hidden cols)
#define JLOC      32       // hidden cols per CTA

// smem layout (floats)
#define HPAD  260          // 16 rows x 260 (pad -> 2-way max bank conflict)
#define GPAD  132
#define SM_W   (HID * NLOC)                 // 32768
#define SM_H   (ROWS * HPAD)                // 4160
#define SM_XP  (ROWS * GPAD)                // 2112
#define SM_G   (ROWS * GPAD)                // 2112
#define SMEM_FLOATS (SM_W + SM_H + SM_XP + SM_G)
#define SMEM_BYTES  (SMEM_FLOATS * 4)       // 164608

// ---------------- persistent device scratch (no runtime allocation) ----------------
__device__ float g_wT_hh[HID * GATES];   // [k][n] : w_hh transposed
__device__ float g_wT_ih[HID * GATES];   // [k][n] : w_ih transposed
__device__ float g_fcwT [LATENT * HID];  // [k][j] : fc_w transposed
__device__ float g_outT [HID * OUTD];    // [k][o] : out_w transposed
__device__ float g_h0   [BATCH * HID];
__device__ float g_xproj[BATCH * GATES];
__device__ float g_hs   [SEQ * BATCH * HID];   // [t][b][j]

// ---------------- packed fp32x2 helpers (sm_100+ dual-rate fp32 path) ----------------
__device__ __forceinline__ unsigned long long pk2(float lo, float hi) {
    unsigned long long r;
    asm("mov.b64 %0, {%1, %2};" : "=l"(r) : "f"(lo), "f"(hi));
    return r;
}
__device__ __forceinline__ void fma2(unsigned long long& d, unsigned long long a,
                                     unsigned long long b) {
    asm("fma.rn.f32x2 %0, %1, %2, %0;" : "+l"(d) : "l"(a), "l"(b));
}
__device__ __forceinline__ float2 upk2(unsigned long long v) {
    float2 r;
    asm("mov.b64 {%0, %1}, %2;" : "=f"(r.x), "=f"(r.y) : "l"(v));
    return r;
}

__device__ __forceinline__ float sigmoid_x(float x) {
    return __frcp_rn(1.f + __expf(-x));
}
__device__ __forceinline__ float tanh_x(float x) {
    // tanh(x) = 1 - 2/(1 + e^{2x}); exact at extremes (e^inf -> 0 contribution)
    return 1.f - 2.f * __frcp_rn(1.f + __expf(2.f * x));
}

// ---------------- generic 32x32 tiled transpose: dst[c*R + r] = src[r*C + c] ----------------
__global__ void transpose_kernel(const float* __restrict__ src, float* __restrict__ dst,
                                 int R, int C) {
    __shared__ float tile[32][33];
    int bx = blockIdx.x * 32;
    int by = blockIdx.y * 32;
    int tx = threadIdx.x & 31;
    int ty = threadIdx.x >> 5;
#pragma unroll
    for (int p = 0; p < 32; p += 8) {
        int r = by + ty + p, c = bx + tx;
        if (r < R && c < C) tile[ty + p][tx] = src[r * C + c];
    }
    __syncthreads();
#pragma unroll
    for (int p = 0; p < 32; p += 8) {
        int r = by + tx, c = bx + ty + p;
        if (r < R && c < C) dst[c * R + r] = tile[tx][ty + p];
    }
}

// ---------------- h0 = z @ fc_w^T + fc_b ----------------
__global__ void h0_kernel(const float* __restrict__ z, const float* __restrict__ fc_b) {
    __shared__ float sh_z[4][LATENT];
    int tid = threadIdx.x;
    int b0 = blockIdx.x * 4;
    {
        int row = tid >> 6, k = tid & 63;
        sh_z[row][k] = z[(b0 + row) * LATENT + k];
    }
    __syncthreads();
    float acc0 = 0.f, acc1 = 0.f, acc2 = 0.f, acc3 = 0.f;
    int j = tid;
#pragma unroll 8
    for (int k = 0; k < LATENT; k++) {
        float w = g_fcwT[k * HID + j];
        acc0 = fmaf(sh_z[0][k], w, acc0);
        acc1 = fmaf(sh_z[1][k], w, acc1);
        acc2 = fmaf(sh_z[2][k], w, acc2);
        acc3 = fmaf(sh_z[3][k], w, acc3);
    }
    float bb = fc_b[j];
    g_h0[(b0 + 0) * HID + j] = acc0 + bb;
    g_h0[(b0 + 1) * HID + j] = acc1 + bb;
    g_h0[(b0 + 2) * HID + j] = acc2 + bb;
    g_h0[(b0 + 3) * HID + j] = acc3 + bb;
}

// ---------------- x_proj = h0 @ w_ih^T + (b_ih + b_hh) ----------------
__global__ void xproj_kernel(const float* __restrict__ b_ih, const float* __restrict__ b_hh) {
    __shared__ float sh_h[32][33];
    __shared__ float sh_w[32][64];
    int tid = threadIdx.x;
    int b0 = blockIdx.x * 32;
    int n0 = blockIdx.y * 64;
    int r  = tid & 31;
    int cg = tid >> 5;
    float acc[8];
#pragma unroll
    for (int i = 0; i < 8; i++) acc[i] = 0.f;

    for (int kc = 0; kc < HID; kc += 32) {
#pragma unroll
        for (int p = 0; p < 4; p++) {
            int e = tid + 256 * p;
            int row = e >> 5, col = e & 31;
            sh_h[row][col] = g_h0[(b0 + row) * HID + kc + col];
        }
#pragma unroll
        for (int p = 0; p < 8; p++) {
            int e = tid + 256 * p;
            int krow = e >> 6, c = e & 63;
            sh_w[krow][c] = g_wT_ih[(kc + krow) * GATES + n0 + c];
        }
        __syncthreads();
#pragma unroll
        for (int kk = 0; kk < 32; kk++) {
            float a = sh_h[r][kk];
            float4 w0 = *reinterpret_cast<const float4*>(&sh_w[kk][cg * 8]);
            float4 w1 = *reinterpret_cast<const float4*>(&sh_w[kk][cg * 8 + 4]);
            acc[0] = fmaf(a, w0.x, acc[0]);
            acc[1] = fmaf(a, w0.y, acc[1]);
            acc[2] = fmaf(a, w0.z, acc[2]);
            acc[3] = fmaf(a, w0.w, acc[3]);
            acc[4] = fmaf(a, w1.x, acc[4]);
            acc[5] = fmaf(a, w1.y, acc[5]);
            acc[6] = fmaf(a, w1.z, acc[6]);
            acc[7] = fmaf(a, w1.w, acc[7]);
        }
        __syncthreads();
    }
#pragma unroll
    for (int i = 0; i < 8; i++) {
        int n = n0 + cg * 8 + i;
        g_xproj[(b0 + r) * GATES + n] = acc[i] + b_ih[n] + b_hh[n];
    }
}

// ---------------- persistent LSTM recurrence ----------------
// 16 clusters x 8 CTAs. Cluster c owns batch rows [16c,16c+16).
// CTA rank owns hidden cols [32*rank, 32*rank+32) -> 128 gate cols (4 gates).
// W_hh slice + x_proj slice smem-resident; c-state in registers.
// Per step: load full h(16x256) from global (written by cluster peers),
// f32x2 GEMM, gate staging, activations, store h slice, barrier.cluster.
__global__ void __launch_bounds__(256, 1) __cluster_dims__(CLUSTER, 1, 1)
lstm_persistent_kernel() {
    extern __shared__ float smem[];
    float* sh_w  = smem;                  // [HID][NLOC]   k-major
    float* sh_h  = sh_w  + SM_W;          // [ROWS][HPAD]
    float* sh_xp = sh_h  + SM_H;          // [ROWS][GPAD]
    float* sh_g  = sh_xp + SM_XP;         // [ROWS][GPAD]

    const int tid  = threadIdx.x;
    const int rank = blockIdx.x & (CLUSTER - 1);
    const int cl   = blockIdx.x / CLUSTER;
    const int b0   = cl * ROWS;
    const int j0   = rank * JLOC;

    // one-time: W_hh slice [256 k][128 n_local], n_local = gate*32 + jj
    for (int idx = tid; idx < HID * NLOC; idx += 256) {
        int k = idx >> 7, nl = idx & 127;
        int g = nl >> 5, jj = nl & 31;
        sh_w[idx] = g_wT_hh[k * GATES + g * HID + j0 + jj];
    }
    // one-time: x_proj slice (same n_local layout, padded rows)
    for (int idx = tid; idx < ROWS * NLOC; idx += 256) {
        int r = idx >> 7, nl = idx & 127;
        int g = nl >> 5, jj = nl & 31;
        sh_xp[r * GPAD + nl] = g_xproj[(b0 + r) * GATES + g * HID + j0 + jj];
    }

    const int r  = tid & 15;    // batch row within cluster tile
    const int cg = tid >> 4;    // 0..15, owns 8 gate cols cg*8..cg*8+7

    float c0 = 0.f, c1 = 0.f;   // cell state for (row=r, jj=cg) and (row=r, jj=cg+16)

    for (int t = 0; t < SEQ; t++) {
        const float* hin = t ? (g_hs + (size_t)(t - 1) * BATCH * HID) : g_h0;
        // load full h for our 16 rows (peers' slices included)
        for (int i = tid; i < ROWS * (HID / 4); i += 256) {
            int row = i >> 6, c4 = i & 63;
            ((float4*)(sh_h + row * HPAD))[c4] =
                ((const float4*)(hin + (size_t)(b0 + row) * HID))[c4];
        }
        __syncthreads();

        // GEMM: gates[r][cg*8..+7] = sum_k h[r][k] * W[k][col]
        unsigned long long acc0 = 0ull, acc1 = 0ull, acc2 = 0ull, acc3 = 0ull;
        const float4* hrow  = (const float4*)(sh_h + r * HPAD);
        const float*  wbase = sh_w + cg * 8;

#define STEP_K(AV, KOFF)                                                        \
        {                                                                       \
            unsigned long long a2 = pk2((AV), (AV));                            \
            const ulonglong2* wp = (const ulonglong2*)(wbase + (KOFF) * NLOC);  \
            ulonglong2 wA = wp[0];                                              \
            ulonglong2 wB = wp[1];                                              \
            fma2(acc0, a2, wA.x);                                               \
            fma2(acc1, a2, wA.y);                                               \
            fma2(acc2, a2, wB.x);                                               \
            fma2(acc3, a2, wB.y);                                               \
        }

#pragma unroll 4
        for (int k4 = 0; k4 < HID / 4; k4++) {
            float4 a4 = hrow[k4];
            STEP_K(a4.x, k4 * 4 + 0)
            STEP_K(a4.y, k4 * 4 + 1)
            STEP_K(a4.z, k4 * 4 + 2)
            STEP_K(a4.w, k4 * 4 + 3)
        }
#undef STEP_K

        // stage gates for cross-gate elementwise update
        {
            unsigned long long* gq = (unsigned long long*)(sh_g + r * GPAD + cg * 8);
            gq[0] = acc0; gq[1] = acc1; gq[2] = acc2; gq[3] = acc3;
        }
        __syncthreads();

        // activations: thread handles (row=r, jj=cg) and (row=r, jj=cg+16)
        {
            const float* gr = sh_g  + r * GPAD;
            const float* xr = sh_xp + r * GPAD;
            float* hdst = g_hs + (size_t)t * BATCH * HID + (size_t)(b0 + r) * HID + j0;

            int jj = cg;
            {
                float gi = gr[jj]      + xr[jj];
                float gf = gr[32 + jj] + xr[32 + jj];
                float gg = gr[64 + jj] + xr[64 + jj];
                float go = gr[96 + jj] + xr[96 + jj];
                float iv = sigmoid_x(gi);
                float fv = sigmoid_x(gf);
                float gv = tanh_x(gg);
                float ov = sigmoid_x(go);
                c0 = fv * c0 + iv * gv;
                hdst[jj] = ov * tanh_x(c0);
            }
            jj = cg + 16;
            {
                float gi = gr[jj]      + xr[jj];
                float gf = gr[32 + jj] + xr[32 + jj];
                float gg = gr[64 + jj] + xr[64 + jj];
                float go = gr[96 + jj] + xr[96 + jj];
                float iv = sigmoid_x(gi);
                float fv = sigmoid_x(gf);
                float gv = tanh_x(gg);
                float ov = sigmoid_x(go);
                c1 = fv * c1 + iv * gv;
                hdst[jj] = ov * tanh_x(c1);
            }
        }

        // cluster barrier: release our h stores, acquire peers' (L1D flushed)
        asm volatile("barrier.cluster.arrive.aligned;" ::: "memory");
        asm volatile("barrier.cluster.wait.aligned;" ::: "memory");
    }
}

// ---------------- output projection (f32x2): out[b][t][o] = hs[t][b][:] . out_w[o][:] + out_b[o] ----------------
__global__ void out_kernel(const float* __restrict__ out_b, float* __restrict__ out) {
    __shared__ float sh_a[64][17];
    __shared__ float sh_w[16][128];
    int tid = threadIdx.x;
    int r0 = blockIdx.x * 64;        // base row into hs flattened [t*256 + b]
    int rr = tid & 15;
    int cg = tid >> 4;               // 0..15 -> 8 cols each

    unsigned long long acc[4][4];
#pragma unroll
    for (int q = 0; q < 4; q++)
#pragma unroll
        for (int i = 0; i < 4; i++) acc[q][i] = 0ull;

    for (int kc = 0; kc < HID; kc += 16) {
#pragma unroll
        for (int p = 0; p < 4; p++) {
            int e = tid + 256 * p;
            int row = e >> 4, kk = e & 15;
            sh_a[row][kk] = g_hs[(size_t)(r0 + row) * HID + kc + kk];
        }
#pragma unroll
        for (int p = 0; p < 8; p++) {
            int e = tid + 256 * p;
            int krow = e >> 7, c = e & 127;
            sh_w[krow][c] = g_outT[(kc + krow) * OUTD + c];
        }
        __syncthreads();
#pragma unroll
        for (int kk = 0; kk < 16; kk++) {
            unsigned long long p0 = pk2(sh_a[rr][kk],      sh_a[rr][kk]);
            unsigned long long p1 = pk2(sh_a[rr + 16][kk], sh_a[rr + 16][kk]);
            unsigned long long p2 = pk2(sh_a[rr + 32][kk], sh_a[rr + 32][kk]);
            unsigned long long p3 = pk2(sh_a[rr + 48][kk], sh_a[rr + 48][kk]);
            const ulonglong2* wp = (const ulonglong2*)(&sh_w[kk][cg * 8]);
            ulonglong2 wA = wp[0];
            ulonglong2 wB = wp[1];
            fma2(acc[0][0], p0, wA.x); fma2(acc[0][1], p0, wA.y);
            fma2(acc[0][2], p0, wB.x); fma2(acc[0][3], p0, wB.y);
            fma2(acc[1][0], p1, wA.x); fma2(acc[1][1], p1, wA.y);
            fma2(acc[1][2], p1, wB.x); fma2(acc[1][3], p1, wB.y);
            fma2(acc[2][0], p2, wA.x); fma2(acc[2][1], p2, wA.y);
            fma2(acc[2][2], p2, wB.x); fma2(acc[2][3], p2, wB.y);
            fma2(acc[3][0], p3, wA.x); fma2(acc[3][1], p3, wA.y);
            fma2(acc[3][2], p3, wB.x); fma2(acc[3][3], p3, wB.y);
        }
        __syncthreads();
    }

    float ob[8];
#pragma unroll
    for (int i = 0; i < 8; i++) ob[i] = out_b[cg * 8 + i];

#pragma unroll
    for (int q = 0; q < 4; q++) {
        int rIdx = r0 + rr + 16 * q;
        int t = rIdx >> 8;           // rIdx = t*256 + b
        int b = rIdx & 255;
        float* dst = out + ((size_t)b * SEQ + t) * OUTD + cg * 8;
#pragma unroll
        for (int i = 0; i < 4; i++) {
            float2 f = upk2(acc[q][i]);
            dst[2 * i]     = f.x + ob[2 * i];
            dst[2 * i + 1] = f.y + ob[2 * i + 1];
        }
    }
}

// ---------------- launch ----------------
extern "C" void kernel_launch(void* const* d_in, const int* in_sizes, int n_in,
                              void* d_out, int out_size) {
    const float* z     = (const float*)d_in[0];
    const float* fc_w  = (const float*)d_in[1];
    const float* fc_b  = (const float*)d_in[2];
    const float* w_ih  = (const float*)d_in[3];
    const float* w_hh  = (const float*)d_in[4];
    const float* b_ih  = (const float*)d_in[5];
    const float* b_hh  = (const float*)d_in[6];
    const float* out_w = (const float*)d_in[7];
    const float* out_b = (const float*)d_in[8];
    float* out = (float*)d_out;

    float *p_wT_hh, *p_wT_ih, *p_fcwT, *p_outT;
    cudaGetSymbolAddress((void**)&p_wT_hh, g_wT_hh);
    cudaGetSymbolAddress((void**)&p_wT_ih, g_wT_ih);
    cudaGetSymbolAddress((void**)&p_fcwT,  g_fcwT);
    cudaGetSymbolAddress((void**)&p_outT,  g_outT);

    cudaFuncSetAttribute(lstm_persistent_kernel,
                         cudaFuncAttributeMaxDynamicSharedMemorySize, SMEM_BYTES);

    // 1) weight reshapes
    transpose_kernel<<<dim3(HID / 32, GATES / 32), 256>>>(w_hh, p_wT_hh, GATES, HID);
    transpose_kernel<<<dim3(HID / 32, GATES / 32), 256>>>(w_ih, p_wT_ih, GATES, HID);
    transpose_kernel<<<dim3(LATENT / 32, HID / 32), 256>>>(fc_w, p_fcwT, HID, LATENT);
    transpose_kernel<<<dim3(HID / 32, OUTD / 32), 256>>>(out_w, p_outT, OUTD, HID);

    // 2) h0
    h0_kernel<<<BATCH / 4, 256>>>(z, fc_b);

    // 3) x_proj
    xproj_kernel<<<dim3(BATCH / 32, GATES / 64), 256>>>(b_ih, b_hh);

    // 4) the whole recurrence in ONE persistent clustered kernel
    lstm_persistent_kernel<<<NCLUSTER * CLUSTER, 256, SMEM_BYTES>>>();

    // 5) output projection
    out_kernel<<<(SEQ * BATCH) / 64, 256>>>(out_b, out);
}

// round 4
// speedup vs baseline: 1.7168x; 1.7168x over previous
#include <cuda_runtime.h>
#include <math.h>

#define BATCH   256
#define LATENT  64
#define HID     256
#define GATES   1024   // 4*HID
#define OUTD    128
#define SEQ     512

#define CLUSTER   8        // CTAs per cluster (hidden split)
#define NCLUSTER  16       // clusters (batch split)
#define ROWS      16       // batch rows per cluster
#define NLOC      128      // gate cols per CTA (4 gates x 32 hidden cols)
#define JLOC      32       // hidden cols per CTA

// smem layout (floats)
#define GPAD   132                          // padded row stride for gate buffers
#define PARTSZ (ROWS * GPAD)                // 2112
#define SM_W   (HID * NLOC)                 // 32768
#define SM_HT  (HID * ROWS)                 // 4096  (h transposed: [k][row])
#define SMEM_FLOATS (SM_W + SM_HT + 4 * PARTSZ + PARTSZ)
#define SMEM_BYTES  (SMEM_FLOATS * 4)       // 189696

// ---------------- persistent device scratch (no runtime allocation) ----------------
__device__ float g_wT_hh[HID * GATES];   // [k][n] : w_hh transposed
__device__ float g_wT_ih[HID * GATES];   // [k][n] : w_ih transposed
__device__ float g_fcwT [LATENT * HID];  // [k][j] : fc_w transposed
__device__ float g_outT [HID * OUTD];    // [k][o] : out_w transposed
__device__ float g_h0   [BATCH * HID];
__device__ float g_xproj[BATCH * GATES];
__device__ float g_hs   [SEQ * BATCH * HID];   // [t][b][j]

// ---------------- packed fp32x2 helpers ----------------
__device__ __forceinline__ unsigned long long pk2(float lo, float hi) {
    unsigned long long r;
    asm("mov.b64 %0, {%1, %2};" : "=l"(r) : "f"(lo), "f"(hi));
    return r;
}
__device__ __forceinline__ void fma2(unsigned long long& d, unsigned long long a,
                                     unsigned long long b) {
    asm("fma.rn.f32x2 %0, %1, %2, %0;" : "+l"(d) : "l"(a), "l"(b));
}
__device__ __forceinline__ float2 upk2(unsigned long long v) {
    float2 r;
    asm("mov.b64 {%0, %1}, %2;" : "=f"(r.x), "=f"(r.y) : "l"(v));
    return r;
}

__device__ __forceinline__ float sigmoid_x(float x) {
    return __frcp_rn(1.f + __expf(-x));
}
__device__ __forceinline__ float tanh_x(float x) {
    return 1.f - 2.f * __frcp_rn(1.f + __expf(2.f * x));
}

// ---------------- generic 32x32 tiled transpose ----------------
__global__ void transpose_kernel(const float* __restrict__ src, float* __restrict__ dst,
                                 int R, int C) {
    __shared__ float tile[32][33];
    int bx = blockIdx.x * 32;
    int by = blockIdx.y * 32;
    int tx = threadIdx.x & 31;
    int ty = threadIdx.x >> 5;
#pragma unroll
    for (int p = 0; p < 32; p += 8) {
        int r = by + ty + p, c = bx + tx;
        if (r < R && c < C) tile[ty + p][tx] = src[r * C + c];
    }
    __syncthreads();
#pragma unroll
    for (int p = 0; p < 32; p += 8) {
        int r = by + tx, c = bx + ty + p;
        if (r < R && c < C) dst[c * R + r] = tile[tx][ty + p];
    }
}

// ---------------- h0 = z @ fc_w^T + fc_b ----------------
__global__ void h0_kernel(const float* __restrict__ z, const float* __restrict__ fc_b) {
    __shared__ float sh_z[4][LATENT];
    int tid = threadIdx.x;
    int b0 = blockIdx.x * 4;
    {
        int row = tid >> 6, k = tid & 63;
        sh_z[row][k] = z[(b0 + row) * LATENT + k];
    }
    __syncthreads();
    float acc0 = 0.f, acc1 = 0.f, acc2 = 0.f, acc3 = 0.f;
    int j = tid;
#pragma unroll 8
    for (int k = 0; k < LATENT; k++) {
        float w = g_fcwT[k * HID + j];
        acc0 = fmaf(sh_z[0][k], w, acc0);
        acc1 = fmaf(sh_z[1][k], w, acc1);
        acc2 = fmaf(sh_z[2][k], w, acc2);
        acc3 = fmaf(sh_z[3][k], w, acc3);
    }
    float bb = fc_b[j];
    g_h0[(b0 + 0) * HID + j] = acc0 + bb;
    g_h0[(b0 + 1) * HID + j] = acc1 + bb;
    g_h0[(b0 + 2) * HID + j] = acc2 + bb;
    g_h0[(b0 + 3) * HID + j] = acc3 + bb;
}

// ---------------- x_proj = h0 @ w_ih^T + (b_ih + b_hh) ----------------
__global__ void xproj_kernel(const float* __restrict__ b_ih, const float* __restrict__ b_hh) {
    __shared__ float sh_h[32][33];
    __shared__ float sh_w[32][64];
    int tid = threadIdx.x;
    int b0 = blockIdx.x * 32;
    int n0 = blockIdx.y * 64;
    int r  = tid & 31;
    int cg = tid >> 5;
    float acc[8];
#pragma unroll
    for (int i = 0; i < 8; i++) acc[i] = 0.f;

    for (int kc = 0; kc < HID; kc += 32) {
#pragma unroll
        for (int p = 0; p < 4; p++) {
            int e = tid + 256 * p;
            int row = e >> 5, col = e & 31;
            sh_h[row][col] = g_h0[(b0 + row) * HID + kc + col];
        }
#pragma unroll
        for (int p = 0; p < 8; p++) {
            int e = tid + 256 * p;
            int krow = e >> 6, c = e & 63;
            sh_w[krow][c] = g_wT_ih[(kc + krow) * GATES + n0 + c];
        }
        __syncthreads();
#pragma unroll
        for (int kk = 0; kk < 32; kk++) {
            float a = sh_h[r][kk];
            float4 w0 = *reinterpret_cast<const float4*>(&sh_w[kk][cg * 8]);
            float4 w1 = *reinterpret_cast<const float4*>(&sh_w[kk][cg * 8 + 4]);
            acc[0] = fmaf(a, w0.x, acc[0]);
            acc[1] = fmaf(a, w0.y, acc[1]);
            acc[2] = fmaf(a, w0.z, acc[2]);
            acc[3] = fmaf(a, w0.w, acc[3]);
            acc[4] = fmaf(a, w1.x, acc[4]);
            acc[5] = fmaf(a, w1.y, acc[5]);
            acc[6] = fmaf(a, w1.z, acc[6]);
            acc[7] = fmaf(a, w1.w, acc[7]);
        }
        __syncthreads();
    }
#pragma unroll
    for (int i = 0; i < 8; i++) {
        int n = n0 + cg * 8 + i;
        g_xproj[(b0 + r) * GATES + n] = acc[i] + b_ih[n] + b_hh[n];
    }
}

// ---------------- persistent LSTM recurrence ----------------
// 16 clusters x 8 CTAs. Cluster owns 16 batch rows; CTA rank owns 32 hidden
// cols (=128 gate cols). Register-blocked GEMM: thread = (cg 0..15, rg 0..3,
// kq 0..3) computes a 4-row x 8-col patch over a 64-wide k slice; 4 k-partials
// reduced through smem, fused with activations. W unique-per-lane (no
// broadcast-wasted LDS wavefronts), reused across 4 rows in registers.
__global__ void __launch_bounds__(256, 1) __cluster_dims__(CLUSTER, 1, 1)
lstm_persistent_kernel() {
    extern __shared__ float smem[];
    float* sh_w    = smem;                       // [HID][NLOC]  k-major
    float* sh_hT   = sh_w + SM_W;                // [HID][ROWS]  h transposed
    float* sh_part = sh_hT + SM_HT;              // [4][ROWS][GPAD]
    float* sh_xp   = sh_part + 4 * PARTSZ;       // [ROWS][GPAD]

    const int tid  = threadIdx.x;
    const int rank = blockIdx.x & (CLUSTER - 1);
    const int cl   = blockIdx.x / CLUSTER;
    const int b0   = cl * ROWS;
    const int j0   = rank * JLOC;

    // one-time: W_hh slice [256 k][128 n_local], n_local = gate*32 + jj
    for (int idx = tid; idx < HID * NLOC; idx += 256) {
        int k = idx >> 7, nl = idx & 127;
        int g = nl >> 5, jj = nl & 31;
        sh_w[idx] = g_wT_hh[k * GATES + g * HID + j0 + jj];
    }
    // one-time: x_proj slice
    for (int idx = tid; idx < ROWS * NLOC; idx += 256) {
        int r = idx >> 7, nl = idx & 127;
        int g = nl >> 5, jj = nl & 31;
        sh_xp[r * GPAD + nl] = g_xproj[(b0 + r) * GATES + g * HID + j0 + jj];
    }

    const int cg = tid & 15;          // col group: 8 gate cols cg*8..+7
    const int rg = (tid >> 4) & 3;    // row group: 4 rows rg*4..+3
    const int kq = tid >> 6;          // k quarter: 64 k values

    // activation assignment: 2 adjacent cells (same row) per thread
    const int arow = tid >> 4;        // (2*tid)>>5
    const int aj   = (2 * tid) & 31;
    float cA = 0.f, cB = 0.f;

    const float* wrow = sh_w  + (kq * 64) * NLOC + cg * 8;
    const float* hrow = sh_hT + (kq * 64) * ROWS + rg * 4;

    for (int t = 0; t < SEQ; t++) {
        const float* hin = t ? (g_hs + (size_t)(t - 1) * BATCH * HID) : g_h0;

        // load our 16 rows of h and transpose into [k][row]
        for (int i = tid; i < ROWS * (HID / 4); i += 256) {   // 4 iters
            int row = i & 15, k4 = i >> 4;
            float4 v = ((const float4*)(hin + (size_t)(b0 + row) * HID))[k4];
            float* d = sh_hT + (k4 * 4) * ROWS + row;
            d[0 * ROWS] = v.x;
            d[1 * ROWS] = v.y;
            d[2 * ROWS] = v.z;
            d[3 * ROWS] = v.w;
        }
        __syncthreads();

        // register-blocked GEMM: 4 rows x 4 col-pairs, k slice of 64
        unsigned long long acc[4][4];
#pragma unroll
        for (int r = 0; r < 4; r++)
#pragma unroll
            for (int c = 0; c < 4; c++) acc[r][c] = 0ull;

#pragma unroll 4
        for (int k = 0; k < 64; k++) {
            float4 hv = *(const float4*)(hrow + k * ROWS);
            unsigned long long a0 = pk2(hv.x, hv.x);
            unsigned long long a1 = pk2(hv.y, hv.y);
            unsigned long long a2 = pk2(hv.z, hv.z);
            unsigned long long a3 = pk2(hv.w, hv.w);
            ulonglong2 wA = *(const ulonglong2*)(wrow + k * NLOC);
            ulonglong2 wB = *(const ulonglong2*)(wrow + k * NLOC + 4);
            fma2(acc[0][0], a0, wA.x); fma2(acc[0][1], a0, wA.y);
            fma2(acc[0][2], a0, wB.x); fma2(acc[0][3], a0, wB.y);
            fma2(acc[1][0], a1, wA.x); fma2(acc[1][1], a1, wA.y);
            fma2(acc[1][2], a1, wB.x); fma2(acc[1][3], a1, wB.y);
            fma2(acc[2][0], a2, wA.x); fma2(acc[2][1], a2, wA.y);
            fma2(acc[2][2], a2, wB.x); fma2(acc[2][3], a2, wB.y);
            fma2(acc[3][0], a3, wA.x); fma2(acc[3][1], a3, wA.y);
            fma2(acc[3][2], a3, wB.x); fma2(acc[3][3], a3, wB.y);
        }

        // store k-partials
        {
            float* pb = sh_part + kq * PARTSZ;
#pragma unroll
            for (int r = 0; r < 4; r++) {
                ulonglong2* d = (ulonglong2*)(pb + (rg * 4 + r) * GPAD + cg * 8);
                d[0] = make_ulonglong2(acc[r][0], acc[r][1]);
                d[1] = make_ulonglong2(acc[r][2], acc[r][3]);
            }
        }
        __syncthreads();

        // reduce 4 partials + x_proj, activations, c/h update (2 cells/thread)
        {
            const float* p0 = sh_part + arow * GPAD;
            const float* p1 = p0 + PARTSZ;
            const float* p2 = p1 + PARTSZ;
            const float* p3 = p2 + PARTSZ;
            const float* xr = sh_xp + arow * GPAD;
            float* hdst = g_hs + (size_t)t * BATCH * HID
                        + (size_t)(b0 + arow) * HID + j0 + aj;

            // cell A (col aj)
            float giA = xr[aj]      + p0[aj]      + p1[aj]      + p2[aj]      + p3[aj];
            float gfA = xr[aj + 32] + p0[aj + 32] + p1[aj + 32] + p2[aj + 32] + p3[aj + 32];
            float ggA = xr[aj + 64] + p0[aj + 64] + p1[aj + 64] + p2[aj + 64] + p3[aj + 64];
            float goA = xr[aj + 96] + p0[aj + 96] + p1[aj + 96] + p2[aj + 96] + p3[aj + 96];
            // cell B (col aj+1)
            int bj = aj + 1;
            float giB = xr[bj]      + p0[bj]      + p1[bj]      + p2[bj]      + p3[bj];
            float gfB = xr[bj + 32] + p0[bj + 32] + p1[bj + 32] + p2[bj + 32] + p3[bj + 32];
            float ggB = xr[bj + 64] + p0[bj + 64] + p1[bj + 64] + p2[bj + 64] + p3[bj + 64];
            float goB = xr[bj + 96] + p0[bj + 96] + p1[bj + 96] + p2[bj + 96] + p3[bj + 96];

            float ivA = sigmoid_x(giA), fvA = sigmoid_x(gfA);
            float gvA = tanh_x(ggA),    ovA = sigmoid_x(goA);
            cA = fvA * cA + ivA * gvA;
            float hA = ovA * tanh_x(cA);

            float ivB = sigmoid_x(giB), fvB = sigmoid_x(gfB);
            float gvB = tanh_x(ggB),    ovB = sigmoid_x(goB);
            cB = fvB * cB + ivB * gvB;
            float hB = ovB * tanh_x(cB);

            *(float2*)hdst = make_float2(hA, hB);
        }

        // cluster barrier: release our h stores, acquire peers'
        asm volatile("barrier.cluster.arrive.aligned;" ::: "memory");
        asm volatile("barrier.cluster.wait.aligned;" ::: "memory");
    }
}

// ---------------- output projection (f32x2) ----------------
__global__ void out_kernel(const float* __restrict__ out_b, float* __restrict__ out) {
    __shared__ float sh_a[64][17];
    __shared__ float sh_w[16][128];
    int tid = threadIdx.x;
    int r0 = blockIdx.x * 64;        // base row into hs flattened [t*256 + b]
    int rr = tid & 15;
    int cg = tid >> 4;               // 0..15 -> 8 cols each

    unsigned long long acc[4][4];
#pragma unroll
    for (int q = 0; q < 4; q++)
#pragma unroll
        for (int i = 0; i < 4; i++) acc[q][i] = 0ull;

    for (int kc = 0; kc < HID; kc += 16) {
#pragma unroll
        for (int p = 0; p < 4; p++) {
            int e = tid + 256 * p;
            int row = e >> 4, kk = e & 15;
            sh_a[row][kk] = g_hs[(size_t)(r0 + row) * HID + kc + kk];
        }
#pragma unroll
        for (int p = 0; p < 8; p++) {
            int e = tid + 256 * p;
            int krow = e >> 7, c = e & 127;
            sh_w[krow][c] = g_outT[(kc + krow) * OUTD + c];
        }
        __syncthreads();
#pragma unroll
        for (int kk = 0; kk < 16; kk++) {
            unsigned long long p0 = pk2(sh_a[rr][kk],      sh_a[rr][kk]);
            unsigned long long p1 = pk2(sh_a[rr + 16][kk], sh_a[rr + 16][kk]);
            unsigned long long p2 = pk2(sh_a[rr + 32][kk], sh_a[rr + 32][kk]);
            unsigned long long p3 = pk2(sh_a[rr + 48][kk], sh_a[rr + 48][kk]);
            const ulonglong2* wp = (const ulonglong2*)(&sh_w[kk][cg * 8]);
            ulonglong2 wA = wp[0];
            ulonglong2 wB = wp[1];
            fma2(acc[0][0], p0, wA.x); fma2(acc[0][1], p0, wA.y);
            fma2(acc[0][2], p0, wB.x); fma2(acc[0][3], p0, wB.y);
            fma2(acc[1][0], p1, wA.x); fma2(acc[1][1], p1, wA.y);
            fma2(acc[1][2], p1, wB.x); fma2(acc[1][3], p1, wB.y);
            fma2(acc[2][0], p2, wA.x); fma2(acc[2][1], p2, wA.y);
            fma2(acc[2][2], p2, wB.x); fma2(acc[2][3], p2, wB.y);
            fma2(acc[3][0], p3, wA.x); fma2(acc[3][1], p3, wA.y);
            fma2(acc[3][2], p3, wB.x); fma2(acc[3][3], p3, wB.y);
        }
        __syncthreads();
    }

    float ob[8];
#pragma unroll
    for (int i = 0; i < 8; i++) ob[i] = out_b[cg * 8 + i];

#pragma unroll
    for (int q = 0; q < 4; q++) {
        int rIdx = r0 + rr + 16 * q;
        int t = rIdx >> 8;           // rIdx = t*256 + b
        int b = rIdx & 255;
        float* dst = out + ((size_t)b * SEQ + t) * OUTD + cg * 8;
#pragma unroll
        for (int i = 0; i < 4; i++) {
            float2 f = upk2(acc[q][i]);
            dst[2 * i]     = f.x + ob[2 * i];
            dst[2 * i + 1] = f.y + ob[2 * i + 1];
        }
    }
}

// ---------------- launch ----------------
extern "C" void kernel_launch(void* const* d_in, const int* in_sizes, int n_in,
                              void* d_out, int out_size) {
    const float* z     = (const float*)d_in[0];
    const float* fc_w  = (const float*)d_in[1];
    const float* fc_b  = (const float*)d_in[2];
    const float* w_ih  = (const float*)d_in[3];
    const float* w_hh  = (const float*)d_in[4];
    const float* b_ih  = (const float*)d_in[5];
    const float* b_hh  = (const float*)d_in[6];
    const float* out_w = (const float*)d_in[7];
    const float* out_b = (const float*)d_in[8];
    float* out = (float*)d_out;

    float *p_wT_hh, *p_wT_ih, *p_fcwT, *p_outT;
    cudaGetSymbolAddress((void**)&p_wT_hh, g_wT_hh);
    cudaGetSymbolAddress((void**)&p_wT_ih, g_wT_ih);
    cudaGetSymbolAddress((void**)&p_fcwT,  g_fcwT);
    cudaGetSymbolAddress((void**)&p_outT,  g_outT);

    cudaFuncSetAttribute(lstm_persistent_kernel,
                         cudaFuncAttributeMaxDynamicSharedMemorySize, SMEM_BYTES);

    // 1) weight reshapes
    transpose_kernel<<<dim3(HID / 32, GATES / 32), 256>>>(w_hh, p_wT_hh, GATES, HID);
    transpose_kernel<<<dim3(HID / 32, GATES / 32), 256>>>(w_ih, p_wT_ih, GATES, HID);
    transpose_kernel<<<dim3(LATENT / 32, HID / 32), 256>>>(fc_w, p_fcwT, HID, LATENT);
    transpose_kernel<<<dim3(HID / 32, OUTD / 32), 256>>>(out_w, p_outT, OUTD, HID);

    // 2) h0
    h0_kernel<<<BATCH / 4, 256>>>(z, fc_b);

    // 3) x_proj
    xproj_kernel<<<dim3(BATCH / 32, GATES / 64), 256>>>(b_ih, b_hh);

    // 4) the whole recurrence in ONE persistent clustered kernel
    lstm_persistent_kernel<<<NCLUSTER * CLUSTER, 256, SMEM_BYTES>>>();

    // 5) output projection
    out_kernel<<<(SEQ * BATCH) / 64, 256>>>(out_b, out);
}

// round 5
// speedup vs baseline: 1.8670x; 1.0875x over previous
#include <cuda_runtime.h>
#include <math.h>

#define BATCH   256
#define LATENT  64
#define HID     256
#define GATES   1024   // 4*HID
#define OUTD    128
#define SEQ     512
#define CHUNK   64     // steps per launch (8 launches)

#define CLUSTER   8        // CTAs per cluster (hidden split)
#define NCLUSTER  16       // clusters (batch split)
#define ROWS      16       // batch rows per cluster
#define NLOC      128      // gate cols per CTA (4 gates x 32 hidden cols)
#define JLOC      32       // hidden cols per CTA

// smem layout (floats)
#define GPAD   132                          // padded row stride for gate buffers
#define PARTSZ (ROWS * GPAD)                // 2112
#define SM_W   (HID * NLOC)                 // 32768
#define SM_HT  (HID * ROWS * 2)             // 8192  (h transposed, duplicated pairs)
#define SMEM_FLOATS (SM_W + SM_HT + 4 * PARTSZ + PARTSZ)
#define SMEM_BYTES  (SMEM_FLOATS * 4)       // 206080

// ---------------- persistent device scratch ----------------
__device__ float g_wT_hh[HID * GATES];   // [k][n]
__device__ float g_wT_ih[HID * GATES];   // [k][n]
__device__ float g_fcwT [LATENT * HID];  // [k][j]
__device__ float g_outT [HID * OUTD];    // [k][o]
__device__ float g_h0   [BATCH * HID];
__device__ float g_c    [BATCH * HID];   // c-state spill between chunks
__device__ float g_xproj[BATCH * GATES];
__device__ float g_hs   [SEQ * BATCH * HID];   // [t][b][j]

// ---------------- packed fp32x2 helpers ----------------
__device__ __forceinline__ unsigned long long pk2(float lo, float hi) {
    unsigned long long r;
    asm("mov.b64 %0, {%1, %2};" : "=l"(r) : "f"(lo), "f"(hi));
    return r;
}
__device__ __forceinline__ void fma2(unsigned long long& d, unsigned long long a,
                                     unsigned long long b) {
    asm("fma.rn.f32x2 %0, %1, %2, %0;" : "+l"(d) : "l"(a), "l"(b));
}
__device__ __forceinline__ float2 upk2(unsigned long long v) {
    float2 r;
    asm("mov.b64 {%0, %1}, %2;" : "=f"(r.x), "=f"(r.y) : "l"(v));
    return r;
}

__device__ __forceinline__ float sigmoid_x(float x) {
    return __frcp_rn(1.f + __expf(-x));
}
__device__ __forceinline__ float tanh_x(float x) {
    return 1.f - 2.f * __frcp_rn(1.f + __expf(2.f * x));
}

// ---------------- generic 32x32 tiled transpose ----------------
__global__ void transpose_kernel(const float* __restrict__ src, float* __restrict__ dst,
                                 int R, int C) {
    __shared__ float tile[32][33];
    int bx = blockIdx.x * 32;
    int by = blockIdx.y * 32;
    int tx = threadIdx.x & 31;
    int ty = threadIdx.x >> 5;
#pragma unroll
    for (int p = 0; p < 32; p += 8) {
        int r = by + ty + p, c = bx + tx;
        if (r < R && c < C) tile[ty + p][tx] = src[r * C + c];
    }
    __syncthreads();
#pragma unroll
    for (int p = 0; p < 32; p += 8) {
        int r = by + tx, c = bx + ty + p;
        if (r < R && c < C) dst[c * R + r] = tile[tx][ty + p];
    }
}

// ---------------- h0 = z @ fc_w^T + fc_b ----------------
__global__ void h0_kernel(const float* __restrict__ z, const float* __restrict__ fc_b) {
    __shared__ float sh_z[4][LATENT];
    int tid = threadIdx.x;
    int b0 = blockIdx.x * 4;
    {
        int row = tid >> 6, k = tid & 63;
        sh_z[row][k] = z[(b0 + row) * LATENT + k];
    }
    __syncthreads();
    float acc0 = 0.f, acc1 = 0.f, acc2 = 0.f, acc3 = 0.f;
    int j = tid;
#pragma unroll 8
    for (int k = 0; k < LATENT; k++) {
        float w = g_fcwT[k * HID + j];
        acc0 = fmaf(sh_z[0][k], w, acc0);
        acc1 = fmaf(sh_z[1][k], w, acc1);
        acc2 = fmaf(sh_z[2][k], w, acc2);
        acc3 = fmaf(sh_z[3][k], w, acc3);
    }
    float bb = fc_b[j];
    g_h0[(b0 + 0) * HID + j] = acc0 + bb;
    g_h0[(b0 + 1) * HID + j] = acc1 + bb;
    g_h0[(b0 + 2) * HID + j] = acc2 + bb;
    g_h0[(b0 + 3) * HID + j] = acc3 + bb;
}

// ---------------- x_proj = h0 @ w_ih^T + (b_ih + b_hh) ----------------
__global__ void xproj_kernel(const float* __restrict__ b_ih, const float* __restrict__ b_hh) {
    __shared__ float sh_h[32][33];
    __shared__ float sh_w[32][64];
    int tid = threadIdx.x;
    int b0 = blockIdx.x * 32;
    int n0 = blockIdx.y * 64;
    int r  = tid & 31;
    int cg = tid >> 5;
    float acc[8];
#pragma unroll
    for (int i = 0; i < 8; i++) acc[i] = 0.f;

    for (int kc = 0; kc < HID; kc += 32) {
#pragma unroll
        for (int p = 0; p < 4; p++) {
            int e = tid + 256 * p;
            int row = e >> 5, col = e & 31;
            sh_h[row][col] = g_h0[(b0 + row) * HID + kc + col];
        }
#pragma unroll
        for (int p = 0; p < 8; p++) {
            int e = tid + 256 * p;
            int krow = e >> 6, c = e & 63;
            sh_w[krow][c] = g_wT_ih[(kc + krow) * GATES + n0 + c];
        }
        __syncthreads();
#pragma unroll
        for (int kk = 0; kk < 32; kk++) {
            float a = sh_h[r][kk];
            float4 w0 = *reinterpret_cast<const float4*>(&sh_w[kk][cg * 8]);
            float4 w1 = *reinterpret_cast<const float4*>(&sh_w[kk][cg * 8 + 4]);
            acc[0] = fmaf(a, w0.x, acc[0]);
            acc[1] = fmaf(a, w0.y, acc[1]);
            acc[2] = fmaf(a, w0.z, acc[2]);
            acc[3] = fmaf(a, w0.w, acc[3]);
            acc[4] = fmaf(a, w1.x, acc[4]);
            acc[5] = fmaf(a, w1.y, acc[5]);
            acc[6] = fmaf(a, w1.z, acc[6]);
            acc[7] = fmaf(a, w1.w, acc[7]);
        }
        __syncthreads();
    }
#pragma unroll
    for (int i = 0; i < 8; i++) {
        int n = n0 + cg * 8 + i;
        g_xproj[(b0 + r) * GATES + n] = acc[i] + b_ih[n] + b_hh[n];
    }
}

// ---------------- persistent LSTM recurrence (one CHUNK of steps) ----------------
// 16 clusters x 8 CTAs; cluster owns 16 batch rows, CTA rank owns 32 hidden
// cols (=128 gate cols). Thread = (cg 0..15, rg 0..3, kq 0..3): 4-row x 8-col
// patch over a 64-wide k slice; 4 k-partials reduced via smem + fused
// activations. h stored in smem as duplicated (h,h) pairs -> packed f32x2
// operands come straight from LDS.128 (no MOV packing). W smem layout permuted
// so each lane's 16B chunks are contiguous (conflict-free LDS).
__global__ void __launch_bounds__(256, 1) __cluster_dims__(CLUSTER, 1, 1)
lstm_persistent_kernel(int t0, int t1) {
    extern __shared__ float smem[];
    float*  sh_w    = smem;                     // [HID][NLOC] permuted
    float2* sh_hT2  = (float2*)(sh_w + SM_W);   // [HID][ROWS] dup pairs
    float*  sh_part = sh_w + SM_W + SM_HT;      // [4][ROWS][GPAD]
    float*  sh_xp   = sh_part + 4 * PARTSZ;     // [ROWS][GPAD]

    const int tid  = threadIdx.x;
    const int rank = blockIdx.x & (CLUSTER - 1);
    const int cl   = blockIdx.x / CLUSTER;
    const int b0   = cl * ROWS;
    const int j0   = rank * JLOC;

    // W_hh slice, permuted: col nl -> (i>>2)*64 + (nl>>3)*4 + (nl&3)
    for (int idx = tid; idx < HID * NLOC; idx += 256) {
        int k = idx >> 7, nl = idx & 127;
        int g = nl >> 5, jj = nl & 31;
        int c8 = nl >> 3, i = nl & 7;
        int dst = (i >> 2) * 64 + c8 * 4 + (i & 3);
        sh_w[k * NLOC + dst] = g_wT_hh[k * GATES + g * HID + j0 + jj];
    }
    // x_proj slice (n_local layout, padded rows)
    for (int idx = tid; idx < ROWS * NLOC; idx += 256) {
        int r = idx >> 7, nl = idx & 127;
        int g = nl >> 5, jj = nl & 31;
        sh_xp[r * GPAD + nl] = g_xproj[(b0 + r) * GATES + g * HID + j0 + jj];
    }

    const int cg = tid & 15;          // col group: 8 gate cols
    const int rg = (tid >> 4) & 3;    // row group: 4 rows
    const int kq = tid >> 6;          // k quarter: 64 k values

    // activation assignment: 2 adjacent cells (same row) per thread
    const int arow = tid >> 4;
    const int aj   = (2 * tid) & 31;

    float cA, cB;
    if (t0 == 0) {
        cA = 0.f; cB = 0.f;
    } else {
        float2 cv = *(const float2*)(g_c + (b0 + arow) * HID + j0 + aj);
        cA = cv.x; cB = cv.y;
    }

    const float*  wrowA = sh_w + (kq * 64) * NLOC + cg * 4;        // cols cg*8..+3
    const float2* hrow  = sh_hT2 + (kq * 64) * ROWS + rg * 4;

    for (int t = t0; t < t1; t++) {
        const float* hin = t ? (g_hs + (size_t)(t - 1) * BATCH * HID) : g_h0;

        // load our 16 rows of h, transpose + duplicate into [k][row] pairs
        for (int i = tid; i < ROWS * (HID / 4); i += 256) {   // 4 iters
            int row = i & 15, k4 = i >> 4;
            float4 v = ((const float4*)(hin + (size_t)(b0 + row) * HID))[k4];
            float2* d = sh_hT2 + (k4 * 4) * ROWS + row;
            d[0 * ROWS] = make_float2(v.x, v.x);
            d[1 * ROWS] = make_float2(v.y, v.y);
            d[2 * ROWS] = make_float2(v.z, v.z);
            d[3 * ROWS] = make_float2(v.w, v.w);
        }
        __syncthreads();

        // register-blocked GEMM: 4 rows x 4 col-pairs, 64-wide k slice
        unsigned long long acc[4][4];
#pragma unroll
        for (int r = 0; r < 4; r++)
#pragma unroll
            for (int c = 0; c < 4; c++) acc[r][c] = 0ull;

#pragma unroll 4
        for (int k = 0; k < 64; k++) {
            const ulonglong2* hp = (const ulonglong2*)(hrow + k * ROWS);
            ulonglong2 h01 = hp[0];          // (h0,h0),(h1,h1)
            ulonglong2 h23 = hp[1];          // (h2,h2),(h3,h3)
            const float* wr = wrowA + k * NLOC;
            ulonglong2 wA = *(const ulonglong2*)(wr);        // cols cg*8..+3
            ulonglong2 wB = *(const ulonglong2*)(wr + 64);   // cols cg*8+4..+7
            fma2(acc[0][0], h01.x, wA.x); fma2(acc[0][1], h01.x, wA.y);
            fma2(acc[0][2], h01.x, wB.x); fma2(acc[0][3], h01.x, wB.y);
            fma2(acc[1][0], h01.y, wA.x); fma2(acc[1][1], h01.y, wA.y);
            fma2(acc[1][2], h01.y, wB.x); fma2(acc[1][3], h01.y, wB.y);
            fma2(acc[2][0], h23.x, wA.x); fma2(acc[2][1], h23.x, wA.y);
            fma2(acc[2][2], h23.x, wB.x); fma2(acc[2][3], h23.x, wB.y);
            fma2(acc[3][0], h23.y, wA.x); fma2(acc[3][1], h23.y, wA.y);
            fma2(acc[3][2], h23.y, wB.x); fma2(acc[3][3], h23.y, wB.y);
        }

        // store k-partials
        {
            float* pb = sh_part + kq * PARTSZ;
#pragma unroll
            for (int r = 0; r < 4; r++) {
                ulonglong2* d = (ulonglong2*)(pb + (rg * 4 + r) * GPAD + cg * 8);
                d[0] = make_ulonglong2(acc[r][0], acc[r][1]);
                d[1] = make_ulonglong2(acc[r][2], acc[r][3]);
            }
        }
        __syncthreads();

        // reduce 4 partials + x_proj, fused activations (2 cells/thread)
        {
            const float* p0 = sh_part + arow * GPAD;
            const float* p1 = p0 + PARTSZ;
            const float* p2 = p1 + PARTSZ;
            const float* p3 = p2 + PARTSZ;
            const float* xr = sh_xp + arow * GPAD;
            float* hdst = g_hs + (size_t)t * BATCH * HID
                        + (size_t)(b0 + arow) * HID + j0 + aj;

            float giA = xr[aj]      + p0[aj]      + p1[aj]      + p2[aj]      + p3[aj];
            float gfA = xr[aj + 32] + p0[aj + 32] + p1[aj + 32] + p2[aj + 32] + p3[aj + 32];
            float ggA = xr[aj + 64] + p0[aj + 64] + p1[aj + 64] + p2[aj + 64] + p3[aj + 64];
            float goA = xr[aj + 96] + p0[aj + 96] + p1[aj + 96] + p2[aj + 96] + p3[aj + 96];
            int bj = aj + 1;
            float giB = xr[bj]      + p0[bj]      + p1[bj]      + p2[bj]      + p3[bj];
            float gfB = xr[bj + 32] + p0[bj + 32] + p1[bj + 32] + p2[bj + 32] + p3[bj + 32];
            float ggB = xr[bj + 64] + p0[bj + 64] + p1[bj + 64] + p2[bj + 64] + p3[bj + 64];
            float goB = xr[bj + 96] + p0[bj + 96] + p1[bj + 96] + p2[bj + 96] + p3[bj + 96];

            float ivA = sigmoid_x(giA), fvA = sigmoid_x(gfA);
            float gvA = tanh_x(ggA),    ovA = sigmoid_x(goA);
            cA = fvA * cA + ivA * gvA;
            float hA = ovA * tanh_x(cA);

            float ivB = sigmoid_x(giB), fvB = sigmoid_x(gfB);
            float gvB = tanh_x(ggB),    ovB = sigmoid_x(goB);
            cB = fvB * cB + ivB * gvB;
            float hB = ovB * tanh_x(cB);

            *(float2*)hdst = make_float2(hA, hB);
        }

        // cluster barrier: release our h stores, acquire peers'
        asm volatile("barrier.cluster.arrive.aligned;" ::: "memory");
        asm volatile("barrier.cluster.wait.aligned;" ::: "memory");
    }

    // spill c-state for the next chunk
    *(float2*)(g_c + (b0 + arow) * HID + j0 + aj) = make_float2(cA, cB);
}

// ---------------- output projection (f32x2, dup pairs + permuted W) ----------------
__global__ void out_kernel(const float* __restrict__ out_b, float* __restrict__ out) {
    __shared__ float2 sh_a2[64][17];      // dup (a,a) pairs, padded
    __shared__ float  sh_w[16][128];      // permuted: (i>>2)*64 + c8*4 + (i&3)
    int tid = threadIdx.x;
    int r0 = blockIdx.x * 64;
    int rr = tid & 15;
    int cg = tid >> 4;               // 0..15 -> 8 cols each

    unsigned long long acc[4][4];
#pragma unroll
    for (int q = 0; q < 4; q++)
#pragma unroll
        for (int i = 0; i < 4; i++) acc[q][i] = 0ull;

    for (int kc = 0; kc < HID; kc += 16) {
#pragma unroll
        for (int p = 0; p < 4; p++) {
            int e = tid + 256 * p;
            int row = e >> 4, kk = e & 15;
            float v = g_hs[(size_t)(r0 + row) * HID + kc + kk];
            sh_a2[row][kk] = make_float2(v, v);
        }
#pragma unroll
        for (int p = 0; p < 8; p++) {
            int e = tid + 256 * p;
            int krow = e >> 7, c = e & 127;
            int c8 = c >> 3, i = c & 7;
            sh_w[krow][(i >> 2) * 64 + c8 * 4 + (i & 3)] = g_outT[(kc + krow) * OUTD + c];
        }
        __syncthreads();
#pragma unroll
        for (int kk = 0; kk < 16; kk++) {
            unsigned long long p0 = *(const unsigned long long*)&sh_a2[rr][kk];
            unsigned long long p1 = *(const unsigned long long*)&sh_a2[rr + 16][kk];
            unsigned long long p2 = *(const unsigned long long*)&sh_a2[rr + 32][kk];
            unsigned long long p3 = *(const unsigned long long*)&sh_a2[rr + 48][kk];
            ulonglong2 wA = *(const ulonglong2*)(&sh_w[kk][cg * 4]);
            ulonglong2 wB = *(const ulonglong2*)(&sh_w[kk][64 + cg * 4]);
            fma2(acc[0][0], p0, wA.x); fma2(acc[0][1], p0, wA.y);
            fma2(acc[0][2], p0, wB.x); fma2(acc[0][3], p0, wB.y);
            fma2(acc[1][0], p1, wA.x); fma2(acc[1][1], p1, wA.y);
            fma2(acc[1][2], p1, wB.x); fma2(acc[1][3], p1, wB.y);
            fma2(acc[2][0], p2, wA.x); fma2(acc[2][1], p2, wA.y);
            fma2(acc[2][2], p2, wB.x); fma2(acc[2][3], p2, wB.y);
            fma2(acc[3][0], p3, wA.x); fma2(acc[3][1], p3, wA.y);
            fma2(acc[3][2], p3, wB.x); fma2(acc[3][3], p3, wB.y);
        }
        __syncthreads();
    }

    float ob[8];
#pragma unroll
    for (int i = 0; i < 8; i++) ob[i] = out_b[cg * 8 + i];

#pragma unroll
    for (int q = 0; q < 4; q++) {
        int rIdx = r0 + rr + 16 * q;
        int t = rIdx >> 8;
        int b = rIdx & 255;
        float* dst = out + ((size_t)b * SEQ + t) * OUTD + cg * 8;
#pragma unroll
        for (int i = 0; i < 4; i++) {
            float2 f = upk2(acc[q][i]);
            dst[2 * i]     = f.x + ob[2 * i];
            dst[2 * i + 1] = f.y + ob[2 * i + 1];
        }
    }
}

// ---------------- launch ----------------
extern "C" void kernel_launch(void* const* d_in, const int* in_sizes, int n_in,
                              void* d_out, int out_size) {
    const float* z     = (const float*)d_in[0];
    const float* fc_w  = (const float*)d_in[1];
    const float* fc_b  = (const float*)d_in[2];
    const float* w_ih  = (const float*)d_in[3];
    const float* w_hh  = (const float*)d_in[4];
    const float* b_ih  = (const float*)d_in[5];
    const float* b_hh  = (const float*)d_in[6];
    const float* out_w = (const float*)d_in[7];
    const float* out_b = (const float*)d_in[8];
    float* out = (float*)d_out;

    float *p_wT_hh, *p_wT_ih, *p_fcwT, *p_outT;
    cudaGetSymbolAddress((void**)&p_wT_hh, g_wT_hh);
    cudaGetSymbolAddress((void**)&p_wT_ih, g_wT_ih);
    cudaGetSymbolAddress((void**)&p_fcwT,  g_fcwT);
    cudaGetSymbolAddress((void**)&p_outT,  g_outT);

    cudaFuncSetAttribute(lstm_persistent_kernel,
                         cudaFuncAttributeMaxDynamicSharedMemorySize, SMEM_BYTES);

    // 1) weight reshapes
    transpose_kernel<<<dim3(HID / 32, GATES / 32), 256>>>(w_hh, p_wT_hh, GATES, HID);
    transpose_kernel<<<dim3(HID / 32, GATES / 32), 256>>>(w_ih, p_wT_ih, GATES, HID);
    transpose_kernel<<<dim3(LATENT / 32, HID / 32), 256>>>(fc_w, p_fcwT, HID, LATENT);
    transpose_kernel<<<dim3(HID / 32, OUTD / 32), 256>>>(out_w, p_outT, OUTD, HID);

    // 2) h0
    h0_kernel<<<BATCH / 4, 256>>>(z, fc_b);

    // 3) x_proj
    xproj_kernel<<<dim3(BATCH / 32, GATES / 64), 256>>>(b_ih, b_hh);

    // 4) the recurrence: 8 persistent-cluster chunks of 64 steps
    for (int c = 0; c < SEQ / CHUNK; c++) {
        lstm_persistent_kernel<<<NCLUSTER * CLUSTER, 256, SMEM_BYTES>>>(
            c * CHUNK, (c + 1) * CHUNK);
    }

    // 5) output projection
    out_kernel<<<(SEQ * BATCH) / 64, 256>>>(out_b, out);
}